// round 16
// baseline (speedup 1.0000x reference)
#include <cuda_runtime.h>
#include <cuda_bf16.h>
#include <cstdint>

#define EPSV 1e-6f

#define BB 8
#define HH 256
#define WW 256
#define CC 64
#define NPIX (BB*HH*WW)

// ---------------------------------------------------------------------------
// Scratch (static __device__ globals per harness rules)
// ---------------------------------------------------------------------------
__device__ __nv_bfloat16 g_t1b[(size_t)NPIX * 256];  // pw1 output (bf16)
__device__ __nv_bfloat16 g_yb [(size_t)NPIX * 128];  // gated dw out (bf16)
__device__ float g_x2[(size_t)NPIX * CC];            // stage-1 residual (fp32)
__device__ float g_part[8192 * 128];                 // GAP partials
__device__ float g_part2[128 * 128];                 // GAP stage-2 partials
__device__ float g_attn[BB * 128];                   // channel attention
// Transposed bf16 weights (n-major rows, k contiguous)
__device__ __align__(16) __nv_bfloat16 g_w1t[256*64];
__device__ __align__(16) __nv_bfloat16 g_w2t[64*128];
__device__ __align__(16) __nv_bfloat16 g_w3t[256*64];   // gate-interleaved rows
__device__ __align__(16) __nv_bfloat16 g_w4t[64*128];

// ---------------------------------------------------------------------------
// Helpers
// ---------------------------------------------------------------------------
__device__ __forceinline__ uint32_t smem_u32(const void* p){
    uint32_t a; asm("{ .reg .u64 t; cvta.to.shared.u64 t, %1; cvt.u32.u64 %0, t; }" : "=r"(a) : "l"(p)); return a;
}
__device__ __forceinline__ void ldsm4(uint32_t* r, uint32_t addr){
    asm volatile("ldmatrix.sync.aligned.m8n8.x4.shared.b16 {%0,%1,%2,%3}, [%4];"
        : "=r"(r[0]), "=r"(r[1]), "=r"(r[2]), "=r"(r[3]) : "r"(addr));
}
__device__ __forceinline__ void ldsm2(uint32_t* r, uint32_t addr){
    asm volatile("ldmatrix.sync.aligned.m8n8.x2.shared.b16 {%0,%1}, [%2];"
        : "=r"(r[0]), "=r"(r[1]) : "r"(addr));
}
__device__ __forceinline__ void mma16816(float* d, const uint32_t* a, const uint32_t* b){
    asm volatile("mma.sync.aligned.m16n8k16.row.col.f32.bf16.bf16.f32 "
        "{%0,%1,%2,%3}, {%4,%5,%6,%7}, {%8,%9}, {%0,%1,%2,%3};"
        : "+f"(d[0]), "+f"(d[1]), "+f"(d[2]), "+f"(d[3])
        : "r"(a[0]), "r"(a[1]), "r"(a[2]), "r"(a[3]), "r"(b[0]), "r"(b[1]));
}
__device__ __forceinline__ uint32_t bfpack(float a, float b){
    __nv_bfloat162 h = __floats2bfloat162_rn(a, b);
    return *(uint32_t*)&h;
}
__device__ __forceinline__ float2 bfunpk(uint32_t u){
    __nv_bfloat162 h = *(__nv_bfloat162*)&u;
    return __bfloat1622float2(h);
}
__device__ __forceinline__ void st_bf2(__nv_bfloat16* p, float a, float b){
    *(__nv_bfloat162*)p = __floats2bfloat162_rn(a, b);
}
__device__ __forceinline__ float4 bf4(uint2 u){
    float2 a = bfunpk(u.x), b = bfunpk(u.y);
    return make_float4(a.x, a.y, b.x, b.y);
}

// ---------------------------------------------------------------------------
// K0: weight prep — transposed bf16 (n-major)
// ---------------------------------------------------------------------------
__global__ void k0_prep(const float* __restrict__ w1, const float* __restrict__ w2,
                        const float* __restrict__ w3, const float* __restrict__ w4)
{
    int idx = blockIdx.x * 256 + threadIdx.x;     // 192*256 = 49152
    if (idx < 16384){                             // w1t [256 n][64 k]
        int n = idx >> 6, k = idx & 63;
        g_w1t[n*64 + k] = __float2bfloat16(w1[k*256 + n]);
    } else if (idx < 24576){                      // w2t [64 n][128 k]
        int i = idx - 16384; int n = i >> 7, k = i & 127;
        g_w2t[n*128 + k] = __float2bfloat16(w2[k*64 + n]);
    } else if (idx < 40960){                      // w3t interleaved [256 n][64 k]
        int i = idx - 24576; int n = i >> 6, k = i & 63;
        g_w3t[n*64 + k] = __float2bfloat16(w3[k*256 + (n & 1)*128 + (n >> 1)]);
    } else {                                      // w4t [64 n][128 k]
        int i = idx - 40960; int n = i >> 7, k = i & 127;
        g_w4t[n*128 + k] = __float2bfloat16(w4[k*64 + n]);
    }
}

// ---------------------------------------------------------------------------
// K1: LN1 + pw1 (64 -> 256) via mma.sync. 128 px/block, 256 threads (8 warps).
// ---------------------------------------------------------------------------
#define K1_SW_OFF   18432
#define K1_PAR_OFF  55296
#define K1_SMEM     56832

__global__ void __launch_bounds__(256) k1_ln_pw1(
    const float* __restrict__ x, const float* __restrict__ g1,
    const float* __restrict__ b1v, const float* __restrict__ bias)
{
    extern __shared__ char smem[];
    uint32_t sb = smem_u32(smem);
    int tid = threadIdx.x, wid = tid >> 5, lane = tid & 31;
    float* sBias = (float*)(smem + K1_PAR_OFF);   // 256
    float* sG  = sBias + 256;                     // 64
    float* sBe = sG + 64;                         // 64

    {
        const uint4* src = (const uint4*)(g_w1t + tid*64);
        uint4* dst = (uint4*)(smem + K1_SW_OFF + tid*144);
        #pragma unroll
        for (int q = 0; q < 8; q++) dst[q] = src[q];
    }
    sBias[tid] = bias[tid];
    if (tid < 64){ sG[tid] = g1[tid]; sBe[tid] = b1v[tid]; }
    __syncthreads();

    size_t P0 = (size_t)blockIdx.x * 128;
    {   // LN: 2 threads per pixel
        int px = tid >> 1, half = tid & 1;
        const float4* xp = (const float4*)(x + (P0 + px) * 64 + half * 32);
        float4 v[8];
        #pragma unroll
        for (int q = 0; q < 8; q++) v[q] = xp[q];
        float s = 0.f, ss = 0.f;
        #pragma unroll
        for (int q = 0; q < 8; q++){
            float4 t = v[q];
            s += t.x + t.y + t.z + t.w;
            ss = fmaf(t.x,t.x, fmaf(t.y,t.y, fmaf(t.z,t.z, fmaf(t.w,t.w, ss))));
        }
        s  += __shfl_xor_sync(0xffffffffu, s, 1);
        ss += __shfl_xor_sync(0xffffffffu, ss, 1);
        float mean = s * (1.f/64.f);
        float var  = fmaf(-mean, mean, ss * (1.f/64.f));
        float rstd = rsqrtf(var + EPSV);
        char* dstrow = smem + px*144 + half*64;
        #pragma unroll
        for (int g = 0; g < 4; g++){
            float4 va = v[2*g], vb = v[2*g+1];
            int c = half*32 + g*8;
            float f0 = fmaf((va.x-mean)*rstd, sG[c+0], sBe[c+0]);
            float f1 = fmaf((va.y-mean)*rstd, sG[c+1], sBe[c+1]);
            float f2 = fmaf((va.z-mean)*rstd, sG[c+2], sBe[c+2]);
            float f3 = fmaf((va.w-mean)*rstd, sG[c+3], sBe[c+3]);
            float f4 = fmaf((vb.x-mean)*rstd, sG[c+4], sBe[c+4]);
            float f5 = fmaf((vb.y-mean)*rstd, sG[c+5], sBe[c+5]);
            float f6 = fmaf((vb.z-mean)*rstd, sG[c+6], sBe[c+6]);
            float f7 = fmaf((vb.w-mean)*rstd, sG[c+7], sBe[c+7]);
            *(uint4*)(dstrow + g*16) = make_uint4(bfpack(f0,f1), bfpack(f2,f3),
                                                  bfpack(f4,f5), bfpack(f6,f7));
        }
    }
    __syncthreads();

    int ns = wid * 32;
    int br = lane & 7, bg = (lane >> 3) & 1;
    uint32_t bfr[4][4][2];
    #pragma unroll
    for (int nt = 0; nt < 4; nt++)
        #pragma unroll
        for (int kt = 0; kt < 4; kt++)
            ldsm2(bfr[nt][kt], sb + K1_SW_OFF + (ns + nt*8 + br)*144 + bg*16 + kt*32);

    int ag = lane >> 3, ar = lane & 7;
    uint32_t abase = sb + (ar + (ag & 1)*8)*144 + (ag >> 1)*16;
    #pragma unroll 1
    for (int mt = 0; mt < 8; mt++){
        uint32_t af[4][4];
        #pragma unroll
        for (int kt = 0; kt < 4; kt++) ldsm4(af[kt], abase + mt*2304 + kt*32);
        float acc[4][4];
        #pragma unroll
        for (int nt = 0; nt < 4; nt++){ acc[nt][0]=0.f; acc[nt][1]=0.f; acc[nt][2]=0.f; acc[nt][3]=0.f; }
        #pragma unroll
        for (int kt = 0; kt < 4; kt++)
            #pragma unroll
            for (int nt = 0; nt < 4; nt++)
                mma16816(acc[nt], af[kt], bfr[nt][kt]);
        int r0 = mt*16 + (lane >> 2);
        int c0 = ns + (lane & 3)*2;
        __nv_bfloat16* o0 = g_t1b + (P0 + r0)*256;
        __nv_bfloat16* o1 = o0 + 8*256;
        #pragma unroll
        for (int nt = 0; nt < 4; nt++){
            int c = c0 + nt*8;
            st_bf2(o0 + c, acc[nt][0] + sBias[c], acc[nt][1] + sBias[c+1]);
            st_bf2(o1 + c, acc[nt][2] + sBias[c], acc[nt][3] + sBias[c+1]);
        }
    }
}

// ---------------------------------------------------------------------------
// K2: depthwise 3x3 + SimpleGate + GAP partials — vectorized 4ch/half/thread.
// ---------------------------------------------------------------------------
__global__ void __launch_bounds__(128) k2_dw_gate(const float* __restrict__ dww, const float* __restrict__ dwb)
{
    int blk = blockIdx.x;             // b*256 + h
    int b   = blk >> 8;
    int h   = blk & 255;
    int seg = threadIdx.x >> 5;       // 0..3 (64-px segment)
    int c4  = threadIdx.x & 31;       // channel quad
    int w0  = seg * 64;
    int cb  = c4 * 4;                 // half0 channel base

    float4 wt0[9], wt1[9];
    #pragma unroll
    for (int i = 0; i < 9; i++){
        wt0[i] = *(const float4*)(dww + i*256 + cb);
        wt1[i] = *(const float4*)(dww + i*256 + 128 + cb);
    }
    float4 bc0 = *(const float4*)(dwb + cb);
    float4 bc1 = *(const float4*)(dwb + 128 + cb);

    const uint2* img = (const uint2*)g_t1b;      // 8B = 4 bf16 ch; row stride 64 uint2/px
    size_t pA = (size_t)(b*256 + h - 1) * 256;   // pixel base of row h-1
    size_t pB = pA + 256, pC = pB + 256;
    bool v0 = (h > 0), v2 = (h < 255);
    const float4 Z = make_float4(0.f,0.f,0.f,0.f);
    #define LD0(pp, wc) bf4(img[((pp) + (size_t)(wc))*64 + c4])
    #define LD1(pp, wc) bf4(img[((pp) + (size_t)(wc))*64 + 32 + c4])

    float4 A0[3][3], A1[3][3];        // [row][wpos]
    {
        int wm = w0 - 1; bool vm = (wm >= 0);
        A0[0][0] = (v0 && vm) ? LD0(pA, wm) : Z;
        A0[1][0] =  vm        ? LD0(pB, wm) : Z;
        A0[2][0] = (v2 && vm) ? LD0(pC, wm) : Z;
        A1[0][0] = (v0 && vm) ? LD1(pA, wm) : Z;
        A1[1][0] =  vm        ? LD1(pB, wm) : Z;
        A1[2][0] = (v2 && vm) ? LD1(pC, wm) : Z;
        A0[0][1] = v0 ? LD0(pA, w0) : Z;
        A0[1][1] =      LD0(pB, w0);
        A0[2][1] = v2 ? LD0(pC, w0) : Z;
        A1[0][1] = v0 ? LD1(pA, w0) : Z;
        A1[1][1] =      LD1(pB, w0);
        A1[2][1] = v2 ? LD1(pC, w0) : Z;
    }
    uint2* yrow = (uint2*)g_yb;       // 8B = 4 gate channels; row stride 32 uint2/px
    float4 gap = Z;
    for (int w = w0; w < w0 + 64; w++){
        int wp = w + 1; bool vp = (wp < 256);
        A0[0][2] = (v0 && vp) ? LD0(pA, wp) : Z;
        A0[1][2] =  vp        ? LD0(pB, wp) : Z;
        A0[2][2] = (v2 && vp) ? LD0(pC, wp) : Z;
        A1[0][2] = (v0 && vp) ? LD1(pA, wp) : Z;
        A1[1][2] =  vp        ? LD1(pB, wp) : Z;
        A1[2][2] = (v2 && vp) ? LD1(pC, wp) : Z;
        float4 a = bc0, c = bc1;
        #pragma unroll
        for (int i = 0; i < 9; i++){
            int rr = i / 3, ww = i % 3;
            a.x = fmaf(A0[rr][ww].x, wt0[i].x, a.x);
            a.y = fmaf(A0[rr][ww].y, wt0[i].y, a.y);
            a.z = fmaf(A0[rr][ww].z, wt0[i].z, a.z);
            a.w = fmaf(A0[rr][ww].w, wt0[i].w, a.w);
            c.x = fmaf(A1[rr][ww].x, wt1[i].x, c.x);
            c.y = fmaf(A1[rr][ww].y, wt1[i].y, c.y);
            c.z = fmaf(A1[rr][ww].z, wt1[i].z, c.z);
            c.w = fmaf(A1[rr][ww].w, wt1[i].w, c.w);
        }
        float4 yv = make_float4(a.x*c.x, a.y*c.y, a.z*c.z, a.w*c.w);
        uint2 pk;
        pk.x = bfpack(yv.x, yv.y);
        pk.y = bfpack(yv.z, yv.w);
        yrow[(pB + (size_t)w)*32 + c4] = pk;
        gap.x += yv.x; gap.y += yv.y; gap.z += yv.z; gap.w += yv.w;
        #pragma unroll
        for (int rr = 0; rr < 3; rr++){
            A0[rr][0] = A0[rr][1]; A0[rr][1] = A0[rr][2];
            A1[rr][0] = A1[rr][1]; A1[rr][1] = A1[rr][2];
        }
    }
    int pid = blk*4 + seg;            // 0..8191
    *(float4*)(g_part + (size_t)pid*128 + cb) = gap;
    #undef LD0
    #undef LD1
}

// ---------------------------------------------------------------------------
// K3a: GAP partial reduce (128 blocks x 128 threads, 64 rows each)
// ---------------------------------------------------------------------------
__global__ void __launch_bounds__(128) k3a_reduce()
{
    int blk = blockIdx.x;
    int c = threadIdx.x;
    const float* p = g_part + (size_t)blk * 64 * 128 + c;
    float s = 0.f;
    #pragma unroll 16
    for (int i = 0; i < 64; i++) s += p[(size_t)i * 128];
    g_part2[blk*128 + c] = s;
}

// ---------------------------------------------------------------------------
// K3b: final GAP reduce + SCA
// ---------------------------------------------------------------------------
__global__ void k3b_sca(const float* __restrict__ scaw, const float* __restrict__ scab)
{
    __shared__ float smn[128];
    int b = blockIdx.x, c = threadIdx.x;
    float s = 0.f;
    #pragma unroll
    for (int i = 0; i < 16; i++) s += g_part2[(b*16 + i)*128 + c];
    smn[c] = s * (1.f / 65536.f);
    __syncthreads();
    float a = scab[c];
    #pragma unroll 8
    for (int k = 0; k < 128; k++) a = fmaf(smn[k], scaw[k*128 + c], a);
    g_attn[b*128 + c] = a;
}

// ---------------------------------------------------------------------------
// K4a: (y*attn) -> pw2 (128 -> 64) -> x2 = x + .*beta. mma.sync.
// Warp tiling: 4 m-groups x 2 n-groups (warp = 2 m-tiles x 32 n), kt-outer —
// cuts per-warp ldmatrix phases 2.1x vs n-slice-8 layout.
// ---------------------------------------------------------------------------
#define K4A_SW_OFF  34816
#define K4A_PAR_OFF 52224
#define K4A_SMEM    53248

__global__ void __launch_bounds__(256) k4a_att_pw2(
    const float* __restrict__ x, const float* __restrict__ b2v, const float* __restrict__ beta)
{
    extern __shared__ char smem[];
    uint32_t sb = smem_u32(smem);
    int tid = threadIdx.x, wid = tid >> 5, lane = tid & 31;
    float* sAttn = (float*)(smem + K4A_PAR_OFF);  // 128
    float* sB2   = sAttn + 128;                   // 64
    float* sBeta = sB2 + 64;                      // 64
    int b = blockIdx.x >> 9;

    {
        int row = tid >> 2, part = tid & 3;
        const uint4* src = (const uint4*)(g_w2t + row*128 + part*32);
        uint4* dst = (uint4*)(smem + K4A_SW_OFF + row*272 + part*64);
        #pragma unroll
        for (int q = 0; q < 4; q++) dst[q] = src[q];
    }
    if (tid < 128) sAttn[tid] = g_attn[b*128 + tid];
    else if (tid < 192) sB2[tid-128] = b2v[tid-128];
    else sBeta[tid-192] = beta[tid-192];
    __syncthreads();

    size_t P0 = (size_t)blockIdx.x * 128;
    {   // stage A = y * attn (bf16, padded rows)
        int row = tid >> 1, half = tid & 1;
        const uint4* src = (const uint4*)(g_yb + (P0 + row)*128 + half*64);
        char* dstrow = smem + row*272 + half*128;
        #pragma unroll
        for (int q = 0; q < 8; q++){
            uint4 raw = src[q];
            const uint32_t* rw = (const uint32_t*)&raw;
            int k0 = half*64 + q*8;
            uint32_t pk[4];
            #pragma unroll
            for (int j = 0; j < 4; j++){
                float2 f = bfunpk(rw[j]);
                f.x *= sAttn[k0 + 2*j]; f.y *= sAttn[k0 + 2*j + 1];
                pk[j] = bfpack(f.x, f.y);
            }
            *(uint4*)(dstrow + q*16) = make_uint4(pk[0], pk[1], pk[2], pk[3]);
        }
    }
    __syncthreads();

    int mg = wid >> 1, ng = wid & 1;
    int n0 = ng * 32;
    int br = lane & 7, bg = (lane >> 3) & 1;
    int ag = lane >> 3, ar = lane & 7;
    uint32_t abase = sb + (ar + (ag & 1)*8)*272 + (ag >> 1)*16 + (mg*2)*4352;
    float acc[2][4][4];
    #pragma unroll
    for (int m = 0; m < 2; m++)
        #pragma unroll
        for (int nt = 0; nt < 4; nt++){
            acc[m][nt][0]=0.f; acc[m][nt][1]=0.f; acc[m][nt][2]=0.f; acc[m][nt][3]=0.f;
        }
    #pragma unroll
    for (int kt = 0; kt < 8; kt++){
        uint32_t af0[4], af1[4];
        ldsm4(af0, abase + kt*32);
        ldsm4(af1, abase + 4352 + kt*32);
        uint32_t bfr[4][2];
        #pragma unroll
        for (int nt = 0; nt < 4; nt++)
            ldsm2(bfr[nt], sb + K4A_SW_OFF + (n0 + nt*8 + br)*272 + bg*16 + kt*32);
        #pragma unroll
        for (int nt = 0; nt < 4; nt++){
            mma16816(acc[0][nt], af0, bfr[nt]);
            mma16816(acc[1][nt], af1, bfr[nt]);
        }
    }
    #pragma unroll
    for (int m = 0; m < 2; m++){
        int r0 = (mg*2 + m)*16 + (lane >> 2);
        #pragma unroll
        for (int nt = 0; nt < 4; nt++){
            int c0 = n0 + nt*8 + (lane & 3)*2;
            const float* a = acc[m][nt];
            float2 xv0 = *(const float2*)(x + (P0 + r0)*64 + c0);
            float2 xv1 = *(const float2*)(x + (P0 + r0 + 8)*64 + c0);
            float2 o0, o1;
            o0.x = fmaf(a[0] + sB2[c0],   sBeta[c0],   xv0.x);
            o0.y = fmaf(a[1] + sB2[c0+1], sBeta[c0+1], xv0.y);
            o1.x = fmaf(a[2] + sB2[c0],   sBeta[c0],   xv1.x);
            o1.y = fmaf(a[3] + sB2[c0+1], sBeta[c0+1], xv1.y);
            *(float2*)(g_x2 + (P0 + r0)*64 + c0)     = o0;
            *(float2*)(g_x2 + (P0 + r0 + 8)*64 + c0) = o1;
        }
    }
}

// ---------------------------------------------------------------------------
// K4b (fused): LN2 -> pw3 -> SimpleGate (smem) -> pw4 -> out.
// Phase 2 uses the 4m x 2n warp tiling.
// ---------------------------------------------------------------------------
#define K4B_SW3_OFF  18432
#define K4B_GT_OFF   55296
#define K4B_SW4_OFF  90112
#define K4B_PAR_OFF  107520
#define K4B_SMEM     109568

__global__ void __launch_bounds__(256) k4b_fused(
    const float* __restrict__ b3v, const float* __restrict__ g2, const float* __restrict__ bb2,
    const float* __restrict__ b4v, const float* __restrict__ gamma, float* __restrict__ out)
{
    extern __shared__ char smem[];
    uint32_t sb = smem_u32(smem);
    int tid = threadIdx.x, wid = tid >> 5, lane = tid & 31;
    float* sB3 = (float*)(smem + K4B_PAR_OFF);    // 256 (interleaved)
    float* sG  = sB3 + 256;                       // 64
    float* sBe = sG + 64;                         // 64
    float* sB4 = sBe + 64;                        // 64
    float* sGa = sB4 + 64;                        // 64

    {
        const uint4* src = (const uint4*)(g_w3t + tid*64);
        uint4* dst = (uint4*)(smem + K4B_SW3_OFF + tid*144);
        #pragma unroll
        for (int q = 0; q < 8; q++) dst[q] = src[q];
    }
    {
        int row = tid >> 2, part = tid & 3;
        const uint4* src = (const uint4*)(g_w4t + row*128 + part*32);
        uint4* dst = (uint4*)(smem + K4B_SW4_OFF + row*272 + part*64);
        #pragma unroll
        for (int q = 0; q < 4; q++) dst[q] = src[q];
    }
    sB3[tid] = b3v[(tid & 1)*128 + (tid >> 1)];
    if (tid < 64){ sG[tid] = g2[tid]; sBe[tid] = bb2[tid]; }
    else if (tid < 128) sB4[tid-64] = b4v[tid-64];
    else if (tid < 192) sGa[tid-128] = gamma[tid-128];
    __syncthreads();

    size_t P0 = (size_t)blockIdx.x * 128;
    {   // LN2 of g_x2 -> A tile
        int px = tid >> 1, half = tid & 1;
        const float4* xp = (const float4*)(g_x2 + (P0 + px) * 64 + half * 32);
        float4 v[8];
        #pragma unroll
        for (int q = 0; q < 8; q++) v[q] = xp[q];
        float s = 0.f, ss = 0.f;
        #pragma unroll
        for (int q = 0; q < 8; q++){
            float4 t = v[q];
            s += t.x + t.y + t.z + t.w;
            ss = fmaf(t.x,t.x, fmaf(t.y,t.y, fmaf(t.z,t.z, fmaf(t.w,t.w, ss))));
        }
        s  += __shfl_xor_sync(0xffffffffu, s, 1);
        ss += __shfl_xor_sync(0xffffffffu, ss, 1);
        float mean = s * (1.f/64.f);
        float var  = fmaf(-mean, mean, ss * (1.f/64.f));
        float rstd = rsqrtf(var + EPSV);
        char* dstrow = smem + px*144 + half*64;
        #pragma unroll
        for (int g = 0; g < 4; g++){
            float4 va = v[2*g], vb = v[2*g+1];
            int c = half*32 + g*8;
            float f0 = fmaf((va.x-mean)*rstd, sG[c+0], sBe[c+0]);
            float f1 = fmaf((va.y-mean)*rstd, sG[c+1], sBe[c+1]);
            float f2 = fmaf((va.z-mean)*rstd, sG[c+2], sBe[c+2]);
            float f3 = fmaf((va.w-mean)*rstd, sG[c+3], sBe[c+3]);
            float f4 = fmaf((vb.x-mean)*rstd, sG[c+4], sBe[c+4]);
            float f5 = fmaf((vb.y-mean)*rstd, sG[c+5], sBe[c+5]);
            float f6 = fmaf((vb.z-mean)*rstd, sG[c+6], sBe[c+6]);
            float f7 = fmaf((vb.w-mean)*rstd, sG[c+7], sBe[c+7]);
            *(uint4*)(dstrow + g*16) = make_uint4(bfpack(f0,f1), bfpack(f2,f3),
                                                  bfpack(f4,f5), bfpack(f6,f7));
        }
    }
    __syncthreads();

    {   // phase 1: pw3 GEMM + gate -> smem
        int ns = wid * 32;
        int br = lane & 7, bg = (lane >> 3) & 1;
        uint32_t bfr[4][4][2];
        #pragma unroll
        for (int nt = 0; nt < 4; nt++)
            #pragma unroll
            for (int kt = 0; kt < 4; kt++)
                ldsm2(bfr[nt][kt], sb + K4B_SW3_OFF + (ns + nt*8 + br)*144 + bg*16 + kt*32);

        int ag = lane >> 3, ar = lane & 7;
        uint32_t abase = sb + (ar + (ag & 1)*8)*144 + (ag >> 1)*16;
        #pragma unroll 1
        for (int mt = 0; mt < 8; mt++){
            uint32_t af[4][4];
            #pragma unroll
            for (int kt = 0; kt < 4; kt++) ldsm4(af[kt], abase + mt*2304 + kt*32);
            float acc[4][4];
            #pragma unroll
            for (int nt = 0; nt < 4; nt++){ acc[nt][0]=0.f; acc[nt][1]=0.f; acc[nt][2]=0.f; acc[nt][3]=0.f; }
            #pragma unroll
            for (int kt = 0; kt < 4; kt++)
                #pragma unroll
                for (int nt = 0; nt < 4; nt++)
                    mma16816(acc[nt], af[kt], bfr[nt][kt]);
            int r0 = mt*16 + (lane >> 2);
            int c0 = ns + (lane & 3)*2;
            char* g0 = smem + K4B_GT_OFF + r0*272;
            char* g1 = g0 + 8*272;
            #pragma unroll
            for (int nt = 0; nt < 4; nt++){
                int c = c0 + nt*8;
                float ga = (acc[nt][0] + sB3[c]) * (acc[nt][1] + sB3[c+1]);
                float gb = (acc[nt][2] + sB3[c]) * (acc[nt][3] + sB3[c+1]);
                *(__nv_bfloat16*)(g0 + (c >> 1)*2) = __float2bfloat16(ga);
                *(__nv_bfloat16*)(g1 + (c >> 1)*2) = __float2bfloat16(gb);
            }
        }
    }
    __syncthreads();

    {   // phase 2: pw4 GEMM (4m x 2n warp tiling) + gamma residual -> out
        int mg = wid >> 1, ng = wid & 1;
        int n0 = ng * 32;
        int br = lane & 7, bg = (lane >> 3) & 1;
        int ag = lane >> 3, ar = lane & 7;
        uint32_t abase = sb + K4B_GT_OFF + (ar + (ag & 1)*8)*272 + (ag >> 1)*16 + (mg*2)*4352;
        float acc[2][4][4];
        #pragma unroll
        for (int m = 0; m < 2; m++)
            #pragma unroll
            for (int nt = 0; nt < 4; nt++){
                acc[m][nt][0]=0.f; acc[m][nt][1]=0.f; acc[m][nt][2]=0.f; acc[m][nt][3]=0.f;
            }
        #pragma unroll
        for (int kt = 0; kt < 8; kt++){
            uint32_t af0[4], af1[4];
            ldsm4(af0, abase + kt*32);
            ldsm4(af1, abase + 4352 + kt*32);
            uint32_t bfr[4][2];
            #pragma unroll
            for (int nt = 0; nt < 4; nt++)
                ldsm2(bfr[nt], sb + K4B_SW4_OFF + (n0 + nt*8 + br)*272 + bg*16 + kt*32);
            #pragma unroll
            for (int nt = 0; nt < 4; nt++){
                mma16816(acc[0][nt], af0, bfr[nt]);
                mma16816(acc[1][nt], af1, bfr[nt]);
            }
        }
        #pragma unroll
        for (int m = 0; m < 2; m++){
            int r0 = (mg*2 + m)*16 + (lane >> 2);
            #pragma unroll
            for (int nt = 0; nt < 4; nt++){
                int c0 = n0 + nt*8 + (lane & 3)*2;
                const float* a = acc[m][nt];
                float2 xv0 = *(const float2*)(g_x2 + (P0 + r0)*64 + c0);
                float2 xv1 = *(const float2*)(g_x2 + (P0 + r0 + 8)*64 + c0);
                float2 o0, o1;
                o0.x = fmaf(a[0] + sB4[c0],   sGa[c0],   xv0.x);
                o0.y = fmaf(a[1] + sB4[c0+1], sGa[c0+1], xv0.y);
                o1.x = fmaf(a[2] + sB4[c0],   sGa[c0],   xv1.x);
                o1.y = fmaf(a[3] + sB4[c0+1], sGa[c0+1], xv1.y);
                *(float2*)(out + (P0 + r0)*64 + c0)     = o0;
                *(float2*)(out + (P0 + r0 + 8)*64 + c0) = o1;
            }
        }
    }
}

// ---------------------------------------------------------------------------
extern "C" void kernel_launch(void* const* d_in, const int* in_sizes, int n_in,
                              void* d_out, int out_size)
{
    const float* x    = (const float*)d_in[0];
    const float* ln1g = (const float*)d_in[1];
    const float* ln1b = (const float*)d_in[2];
    const float* pw1w = (const float*)d_in[3];
    const float* pw1b = (const float*)d_in[4];
    const float* dww  = (const float*)d_in[5];
    const float* dwb  = (const float*)d_in[6];
    const float* scaw = (const float*)d_in[7];
    const float* scab = (const float*)d_in[8];
    const float* pw2w = (const float*)d_in[9];
    const float* pw2b = (const float*)d_in[10];
    const float* beta = (const float*)d_in[11];
    const float* ln2g = (const float*)d_in[12];
    const float* ln2b = (const float*)d_in[13];
    const float* pw3w = (const float*)d_in[14];
    const float* pw3b = (const float*)d_in[15];
    const float* pw4w = (const float*)d_in[16];
    const float* pw4b = (const float*)d_in[17];
    const float* gam  = (const float*)d_in[18];
    float* out = (float*)d_out;

    cudaFuncSetAttribute(k1_ln_pw1,   cudaFuncAttributeMaxDynamicSharedMemorySize, K1_SMEM);
    cudaFuncSetAttribute(k4a_att_pw2, cudaFuncAttributeMaxDynamicSharedMemorySize, K4A_SMEM);
    cudaFuncSetAttribute(k4b_fused,   cudaFuncAttributeMaxDynamicSharedMemorySize, K4B_SMEM);

    k0_prep    <<<192, 256>>>(pw1w, pw2w, pw3w, pw4w);
    k1_ln_pw1  <<<NPIX/128, 256, K1_SMEM>>>(x, ln1g, ln1b, pw1b);
    k2_dw_gate <<<2048, 128>>>(dww, dwb);
    k3a_reduce <<<128, 128>>>();
    k3b_sca    <<<BB, 128>>>(scaw, scab);
    k4a_att_pw2<<<NPIX/128, 256, K4A_SMEM>>>(x, pw2b, beta);
    k4b_fused  <<<NPIX/128, 256, K4B_SMEM>>>(pw3b, ln2g, ln2b, pw4b, gam, out);
}

// round 17
// speedup vs baseline: 1.3679x; 1.3679x over previous
#include <cuda_runtime.h>
#include <cuda_bf16.h>
#include <cstdint>

#define EPSV 1e-6f

#define BB 8
#define HH 256
#define WW 256
#define CC 64
#define NPIX (BB*HH*WW)

// ---------------------------------------------------------------------------
// Scratch (static __device__ globals per harness rules)
// ---------------------------------------------------------------------------
__device__ __nv_bfloat16 g_t1b[(size_t)NPIX * 256];  // pw1 output (bf16)
__device__ __nv_bfloat16 g_yb [(size_t)NPIX * 128];  // gated dw out (bf16)
__device__ float g_x2[(size_t)NPIX * CC];            // stage-1 residual (fp32)
__device__ float g_part[8192 * 128];                 // GAP partials
__device__ float g_part2[128 * 128];                 // GAP stage-2 partials
__device__ float g_attn[BB * 128];                   // channel attention
// Transposed bf16 weights (n-major rows, k contiguous)
__device__ __align__(16) __nv_bfloat16 g_w1t[256*64];
__device__ __align__(16) __nv_bfloat16 g_w2t[64*128];
__device__ __align__(16) __nv_bfloat16 g_w3t[256*64];   // gate-interleaved rows
__device__ __align__(16) __nv_bfloat16 g_w4t[64*128];

// ---------------------------------------------------------------------------
// Helpers
// ---------------------------------------------------------------------------
__device__ __forceinline__ uint32_t smem_u32(const void* p){
    uint32_t a; asm("{ .reg .u64 t; cvta.to.shared.u64 t, %1; cvt.u32.u64 %0, t; }" : "=r"(a) : "l"(p)); return a;
}
__device__ __forceinline__ void ldsm4(uint32_t* r, uint32_t addr){
    asm volatile("ldmatrix.sync.aligned.m8n8.x4.shared.b16 {%0,%1,%2,%3}, [%4];"
        : "=r"(r[0]), "=r"(r[1]), "=r"(r[2]), "=r"(r[3]) : "r"(addr));
}
__device__ __forceinline__ void ldsm2(uint32_t* r, uint32_t addr){
    asm volatile("ldmatrix.sync.aligned.m8n8.x2.shared.b16 {%0,%1}, [%2];"
        : "=r"(r[0]), "=r"(r[1]) : "r"(addr));
}
__device__ __forceinline__ void mma16816(float* d, const uint32_t* a, const uint32_t* b){
    asm volatile("mma.sync.aligned.m16n8k16.row.col.f32.bf16.bf16.f32 "
        "{%0,%1,%2,%3}, {%4,%5,%6,%7}, {%8,%9}, {%0,%1,%2,%3};"
        : "+f"(d[0]), "+f"(d[1]), "+f"(d[2]), "+f"(d[3])
        : "r"(a[0]), "r"(a[1]), "r"(a[2]), "r"(a[3]), "r"(b[0]), "r"(b[1]));
}
__device__ __forceinline__ uint32_t bfpack(float a, float b){
    __nv_bfloat162 h = __floats2bfloat162_rn(a, b);
    return *(uint32_t*)&h;
}
__device__ __forceinline__ float2 bfunpk(uint32_t u){
    __nv_bfloat162 h = *(__nv_bfloat162*)&u;
    return __bfloat1622float2(h);
}
__device__ __forceinline__ void st_bf2(__nv_bfloat16* p, float a, float b){
    *(__nv_bfloat162*)p = __floats2bfloat162_rn(a, b);
}
__device__ __forceinline__ float4 bf4(uint2 u){
    float2 a = bfunpk(u.x), b = bfunpk(u.y);
    return make_float4(a.x, a.y, b.x, b.y);
}

// ---------------------------------------------------------------------------
// K0: weight prep — transposed bf16 (n-major)
// ---------------------------------------------------------------------------
__global__ void k0_prep(const float* __restrict__ w1, const float* __restrict__ w2,
                        const float* __restrict__ w3, const float* __restrict__ w4)
{
    int idx = blockIdx.x * 256 + threadIdx.x;     // 192*256 = 49152
    if (idx < 16384){                             // w1t [256 n][64 k]
        int n = idx >> 6, k = idx & 63;
        g_w1t[n*64 + k] = __float2bfloat16(w1[k*256 + n]);
    } else if (idx < 24576){                      // w2t [64 n][128 k]
        int i = idx - 16384; int n = i >> 7, k = i & 127;
        g_w2t[n*128 + k] = __float2bfloat16(w2[k*64 + n]);
    } else if (idx < 40960){                      // w3t interleaved [256 n][64 k]
        int i = idx - 24576; int n = i >> 6, k = i & 63;
        g_w3t[n*64 + k] = __float2bfloat16(w3[k*256 + (n & 1)*128 + (n >> 1)]);
    } else {                                      // w4t [64 n][128 k]
        int i = idx - 40960; int n = i >> 7, k = i & 127;
        g_w4t[n*128 + k] = __float2bfloat16(w4[k*64 + n]);
    }
}

// ---------------------------------------------------------------------------
// K1: LN1 + pw1 (64 -> 256) via mma.sync. 128 px/block, 256 threads (8 warps).
// __launch_bounds__(256,3): cap regs at 85 to lift occupancy 2 -> 3 blocks/SM.
// ---------------------------------------------------------------------------
#define K1_SW_OFF   18432
#define K1_PAR_OFF  55296
#define K1_SMEM     56832

__global__ void __launch_bounds__(256, 3) k1_ln_pw1(
    const float* __restrict__ x, const float* __restrict__ g1,
    const float* __restrict__ b1v, const float* __restrict__ bias)
{
    extern __shared__ char smem[];
    uint32_t sb = smem_u32(smem);
    int tid = threadIdx.x, wid = tid >> 5, lane = tid & 31;
    float* sBias = (float*)(smem + K1_PAR_OFF);   // 256
    float* sG  = sBias + 256;                     // 64
    float* sBe = sG + 64;                         // 64

    {
        const uint4* src = (const uint4*)(g_w1t + tid*64);
        uint4* dst = (uint4*)(smem + K1_SW_OFF + tid*144);
        #pragma unroll
        for (int q = 0; q < 8; q++) dst[q] = src[q];
    }
    sBias[tid] = bias[tid];
    if (tid < 64){ sG[tid] = g1[tid]; sBe[tid] = b1v[tid]; }
    __syncthreads();

    size_t P0 = (size_t)blockIdx.x * 128;
    {   // LN: 2 threads per pixel
        int px = tid >> 1, half = tid & 1;
        const float4* xp = (const float4*)(x + (P0 + px) * 64 + half * 32);
        float4 v[8];
        #pragma unroll
        for (int q = 0; q < 8; q++) v[q] = xp[q];
        float s = 0.f, ss = 0.f;
        #pragma unroll
        for (int q = 0; q < 8; q++){
            float4 t = v[q];
            s += t.x + t.y + t.z + t.w;
            ss = fmaf(t.x,t.x, fmaf(t.y,t.y, fmaf(t.z,t.z, fmaf(t.w,t.w, ss))));
        }
        s  += __shfl_xor_sync(0xffffffffu, s, 1);
        ss += __shfl_xor_sync(0xffffffffu, ss, 1);
        float mean = s * (1.f/64.f);
        float var  = fmaf(-mean, mean, ss * (1.f/64.f));
        float rstd = rsqrtf(var + EPSV);
        char* dstrow = smem + px*144 + half*64;
        #pragma unroll
        for (int g = 0; g < 4; g++){
            float4 va = v[2*g], vb = v[2*g+1];
            int c = half*32 + g*8;
            float f0 = fmaf((va.x-mean)*rstd, sG[c+0], sBe[c+0]);
            float f1 = fmaf((va.y-mean)*rstd, sG[c+1], sBe[c+1]);
            float f2 = fmaf((va.z-mean)*rstd, sG[c+2], sBe[c+2]);
            float f3 = fmaf((va.w-mean)*rstd, sG[c+3], sBe[c+3]);
            float f4 = fmaf((vb.x-mean)*rstd, sG[c+4], sBe[c+4]);
            float f5 = fmaf((vb.y-mean)*rstd, sG[c+5], sBe[c+5]);
            float f6 = fmaf((vb.z-mean)*rstd, sG[c+6], sBe[c+6]);
            float f7 = fmaf((vb.w-mean)*rstd, sG[c+7], sBe[c+7]);
            *(uint4*)(dstrow + g*16) = make_uint4(bfpack(f0,f1), bfpack(f2,f3),
                                                  bfpack(f4,f5), bfpack(f6,f7));
        }
    }
    __syncthreads();

    int ns = wid * 32;
    int br = lane & 7, bg = (lane >> 3) & 1;
    uint32_t bfr[4][4][2];
    #pragma unroll
    for (int nt = 0; nt < 4; nt++)
        #pragma unroll
        for (int kt = 0; kt < 4; kt++)
            ldsm2(bfr[nt][kt], sb + K1_SW_OFF + (ns + nt*8 + br)*144 + bg*16 + kt*32);

    int ag = lane >> 3, ar = lane & 7;
    uint32_t abase = sb + (ar + (ag & 1)*8)*144 + (ag >> 1)*16;
    #pragma unroll 1
    for (int mt = 0; mt < 8; mt++){
        uint32_t af[4][4];
        #pragma unroll
        for (int kt = 0; kt < 4; kt++) ldsm4(af[kt], abase + mt*2304 + kt*32);
        float acc[4][4];
        #pragma unroll
        for (int nt = 0; nt < 4; nt++){ acc[nt][0]=0.f; acc[nt][1]=0.f; acc[nt][2]=0.f; acc[nt][3]=0.f; }
        #pragma unroll
        for (int kt = 0; kt < 4; kt++)
            #pragma unroll
            for (int nt = 0; nt < 4; nt++)
                mma16816(acc[nt], af[kt], bfr[nt][kt]);
        int r0 = mt*16 + (lane >> 2);
        int c0 = ns + (lane & 3)*2;
        __nv_bfloat16* o0 = g_t1b + (P0 + r0)*256;
        __nv_bfloat16* o1 = o0 + 8*256;
        #pragma unroll
        for (int nt = 0; nt < 4; nt++){
            int c = c0 + nt*8;
            st_bf2(o0 + c, acc[nt][0] + sBias[c], acc[nt][1] + sBias[c+1]);
            st_bf2(o1 + c, acc[nt][2] + sBias[c], acc[nt][3] + sBias[c+1]);
        }
    }
}

// ---------------------------------------------------------------------------
// K2: depthwise 3x3 + SimpleGate + GAP partials — vectorized 4ch/half/thread.
// ---------------------------------------------------------------------------
__global__ void __launch_bounds__(128) k2_dw_gate(const float* __restrict__ dww, const float* __restrict__ dwb)
{
    int blk = blockIdx.x;             // b*256 + h
    int b   = blk >> 8;
    int h   = blk & 255;
    int seg = threadIdx.x >> 5;       // 0..3 (64-px segment)
    int c4  = threadIdx.x & 31;       // channel quad
    int w0  = seg * 64;
    int cb  = c4 * 4;                 // half0 channel base

    float4 wt0[9], wt1[9];
    #pragma unroll
    for (int i = 0; i < 9; i++){
        wt0[i] = *(const float4*)(dww + i*256 + cb);
        wt1[i] = *(const float4*)(dww + i*256 + 128 + cb);
    }
    float4 bc0 = *(const float4*)(dwb + cb);
    float4 bc1 = *(const float4*)(dwb + 128 + cb);

    const uint2* img = (const uint2*)g_t1b;      // 8B = 4 bf16 ch; row stride 64 uint2/px
    size_t pA = (size_t)(b*256 + h - 1) * 256;   // pixel base of row h-1
    size_t pB = pA + 256, pC = pB + 256;
    bool v0 = (h > 0), v2 = (h < 255);
    const float4 Z = make_float4(0.f,0.f,0.f,0.f);
    #define LD0(pp, wc) bf4(img[((pp) + (size_t)(wc))*64 + c4])
    #define LD1(pp, wc) bf4(img[((pp) + (size_t)(wc))*64 + 32 + c4])

    float4 A0[3][3], A1[3][3];        // [row][wpos]
    {
        int wm = w0 - 1; bool vm = (wm >= 0);
        A0[0][0] = (v0 && vm) ? LD0(pA, wm) : Z;
        A0[1][0] =  vm        ? LD0(pB, wm) : Z;
        A0[2][0] = (v2 && vm) ? LD0(pC, wm) : Z;
        A1[0][0] = (v0 && vm) ? LD1(pA, wm) : Z;
        A1[1][0] =  vm        ? LD1(pB, wm) : Z;
        A1[2][0] = (v2 && vm) ? LD1(pC, wm) : Z;
        A0[0][1] = v0 ? LD0(pA, w0) : Z;
        A0[1][1] =      LD0(pB, w0);
        A0[2][1] = v2 ? LD0(pC, w0) : Z;
        A1[0][1] = v0 ? LD1(pA, w0) : Z;
        A1[1][1] =      LD1(pB, w0);
        A1[2][1] = v2 ? LD1(pC, w0) : Z;
    }
    uint2* yrow = (uint2*)g_yb;       // 8B = 4 gate channels; row stride 32 uint2/px
    float4 gap = Z;
    for (int w = w0; w < w0 + 64; w++){
        int wp = w + 1; bool vp = (wp < 256);
        A0[0][2] = (v0 && vp) ? LD0(pA, wp) : Z;
        A0[1][2] =  vp        ? LD0(pB, wp) : Z;
        A0[2][2] = (v2 && vp) ? LD0(pC, wp) : Z;
        A1[0][2] = (v0 && vp) ? LD1(pA, wp) : Z;
        A1[1][2] =  vp        ? LD1(pB, wp) : Z;
        A1[2][2] = (v2 && vp) ? LD1(pC, wp) : Z;
        float4 a = bc0, c = bc1;
        #pragma unroll
        for (int i = 0; i < 9; i++){
            int rr = i / 3, ww = i % 3;
            a.x = fmaf(A0[rr][ww].x, wt0[i].x, a.x);
            a.y = fmaf(A0[rr][ww].y, wt0[i].y, a.y);
            a.z = fmaf(A0[rr][ww].z, wt0[i].z, a.z);
            a.w = fmaf(A0[rr][ww].w, wt0[i].w, a.w);
            c.x = fmaf(A1[rr][ww].x, wt1[i].x, c.x);
            c.y = fmaf(A1[rr][ww].y, wt1[i].y, c.y);
            c.z = fmaf(A1[rr][ww].z, wt1[i].z, c.z);
            c.w = fmaf(A1[rr][ww].w, wt1[i].w, c.w);
        }
        float4 yv = make_float4(a.x*c.x, a.y*c.y, a.z*c.z, a.w*c.w);
        uint2 pk;
        pk.x = bfpack(yv.x, yv.y);
        pk.y = bfpack(yv.z, yv.w);
        yrow[(pB + (size_t)w)*32 + c4] = pk;
        gap.x += yv.x; gap.y += yv.y; gap.z += yv.z; gap.w += yv.w;
        #pragma unroll
        for (int rr = 0; rr < 3; rr++){
            A0[rr][0] = A0[rr][1]; A0[rr][1] = A0[rr][2];
            A1[rr][0] = A1[rr][1]; A1[rr][1] = A1[rr][2];
        }
    }
    int pid = blk*4 + seg;            // 0..8191
    *(float4*)(g_part + (size_t)pid*128 + cb) = gap;
    #undef LD0
    #undef LD1
}

// ---------------------------------------------------------------------------
// K3a: GAP partial reduce (128 blocks x 128 threads, 64 rows each)
// ---------------------------------------------------------------------------
__global__ void __launch_bounds__(128) k3a_reduce()
{
    int blk = blockIdx.x;
    int c = threadIdx.x;
    const float* p = g_part + (size_t)blk * 64 * 128 + c;
    float s = 0.f;
    #pragma unroll 16
    for (int i = 0; i < 64; i++) s += p[(size_t)i * 128];
    g_part2[blk*128 + c] = s;
}

// ---------------------------------------------------------------------------
// K3b: final GAP reduce + SCA
// ---------------------------------------------------------------------------
__global__ void k3b_sca(const float* __restrict__ scaw, const float* __restrict__ scab)
{
    __shared__ float smn[128];
    int b = blockIdx.x, c = threadIdx.x;
    float s = 0.f;
    #pragma unroll
    for (int i = 0; i < 16; i++) s += g_part2[(b*16 + i)*128 + c];
    smn[c] = s * (1.f / 65536.f);
    __syncthreads();
    float a = scab[c];
    #pragma unroll 8
    for (int k = 0; k < 128; k++) a = fmaf(smn[k], scaw[k*128 + c], a);
    g_attn[b*128 + c] = a;
}

// ---------------------------------------------------------------------------
// K4a: (y*attn) -> pw2 (128 -> 64) -> x2 = x + .*beta. mma.sync, warp n-slice 8.
// __launch_bounds__(256,3): lift reg-limited occupancy 2 -> 3 blocks/SM.
// ---------------------------------------------------------------------------
#define K4A_SW_OFF  34816
#define K4A_PAR_OFF 52224
#define K4A_SMEM    53248

__global__ void __launch_bounds__(256, 3) k4a_att_pw2(
    const float* __restrict__ x, const float* __restrict__ b2v, const float* __restrict__ beta)
{
    extern __shared__ char smem[];
    uint32_t sb = smem_u32(smem);
    int tid = threadIdx.x, wid = tid >> 5, lane = tid & 31;
    float* sAttn = (float*)(smem + K4A_PAR_OFF);  // 128
    float* sB2   = sAttn + 128;                   // 64
    float* sBeta = sB2 + 64;                      // 64
    int b = blockIdx.x >> 9;

    {
        int row = tid >> 2, part = tid & 3;
        const uint4* src = (const uint4*)(g_w2t + row*128 + part*32);
        uint4* dst = (uint4*)(smem + K4A_SW_OFF + row*272 + part*64);
        #pragma unroll
        for (int q = 0; q < 4; q++) dst[q] = src[q];
    }
    if (tid < 128) sAttn[tid] = g_attn[b*128 + tid];
    else if (tid < 192) sB2[tid-128] = b2v[tid-128];
    else sBeta[tid-192] = beta[tid-192];
    __syncthreads();

    size_t P0 = (size_t)blockIdx.x * 128;
    {   // stage A = y * attn (bf16, padded rows)
        int row = tid >> 1, half = tid & 1;
        const uint4* src = (const uint4*)(g_yb + (P0 + row)*128 + half*64);
        char* dstrow = smem + row*272 + half*128;
        #pragma unroll
        for (int q = 0; q < 8; q++){
            uint4 raw = src[q];
            const uint32_t* rw = (const uint32_t*)&raw;
            int k0 = half*64 + q*8;
            uint32_t pk[4];
            #pragma unroll
            for (int j = 0; j < 4; j++){
                float2 f = bfunpk(rw[j]);
                f.x *= sAttn[k0 + 2*j]; f.y *= sAttn[k0 + 2*j + 1];
                pk[j] = bfpack(f.x, f.y);
            }
            *(uint4*)(dstrow + q*16) = make_uint4(pk[0], pk[1], pk[2], pk[3]);
        }
    }
    __syncthreads();

    int n0 = wid * 8;
    int br = lane & 7, bg = (lane >> 3) & 1;
    uint32_t bfr[8][2];
    #pragma unroll
    for (int kt = 0; kt < 8; kt++)
        ldsm2(bfr[kt], sb + K4A_SW_OFF + (n0 + br)*272 + bg*16 + kt*32);

    int ag = lane >> 3, ar = lane & 7;
    uint32_t abase = sb + (ar + (ag & 1)*8)*272 + (ag >> 1)*16;
    #pragma unroll 1
    for (int mt = 0; mt < 8; mt++){
        uint32_t af[8][4];
        #pragma unroll
        for (int kt = 0; kt < 8; kt++) ldsm4(af[kt], abase + mt*4352 + kt*32);
        float acc[4] = {0.f, 0.f, 0.f, 0.f};
        #pragma unroll
        for (int kt = 0; kt < 8; kt++) mma16816(acc, af[kt], bfr[kt]);
        int r0 = mt*16 + (lane >> 2);
        int c0 = n0 + (lane & 3)*2;
        float2 xv0 = *(const float2*)(x + (P0 + r0)*64 + c0);
        float2 xv1 = *(const float2*)(x + (P0 + r0 + 8)*64 + c0);
        float2 o0, o1;
        o0.x = fmaf(acc[0] + sB2[c0],   sBeta[c0],   xv0.x);
        o0.y = fmaf(acc[1] + sB2[c0+1], sBeta[c0+1], xv0.y);
        o1.x = fmaf(acc[2] + sB2[c0],   sBeta[c0],   xv1.x);
        o1.y = fmaf(acc[3] + sB2[c0+1], sBeta[c0+1], xv1.y);
        *(float2*)(g_x2 + (P0 + r0)*64 + c0)     = o0;
        *(float2*)(g_x2 + (P0 + r0 + 8)*64 + c0) = o1;
    }
}

// ---------------------------------------------------------------------------
// K4b (fused): LN2 -> pw3 -> SimpleGate (smem) -> pw4 -> out.
// smem 109568 caps at 2 blocks/SM; keep default bounds.
// ---------------------------------------------------------------------------
#define K4B_SW3_OFF  18432
#define K4B_GT_OFF   55296
#define K4B_SW4_OFF  90112
#define K4B_PAR_OFF  107520
#define K4B_SMEM     109568

__global__ void __launch_bounds__(256) k4b_fused(
    const float* __restrict__ b3v, const float* __restrict__ g2, const float* __restrict__ bb2,
    const float* __restrict__ b4v, const float* __restrict__ gamma, float* __restrict__ out)
{
    extern __shared__ char smem[];
    uint32_t sb = smem_u32(smem);
    int tid = threadIdx.x, wid = tid >> 5, lane = tid & 31;
    float* sB3 = (float*)(smem + K4B_PAR_OFF);    // 256 (interleaved)
    float* sG  = sB3 + 256;                       // 64
    float* sBe = sG + 64;                         // 64
    float* sB4 = sBe + 64;                        // 64
    float* sGa = sB4 + 64;                        // 64

    {
        const uint4* src = (const uint4*)(g_w3t + tid*64);
        uint4* dst = (uint4*)(smem + K4B_SW3_OFF + tid*144);
        #pragma unroll
        for (int q = 0; q < 8; q++) dst[q] = src[q];
    }
    {
        int row = tid >> 2, part = tid & 3;
        const uint4* src = (const uint4*)(g_w4t + row*128 + part*32);
        uint4* dst = (uint4*)(smem + K4B_SW4_OFF + row*272 + part*64);
        #pragma unroll
        for (int q = 0; q < 4; q++) dst[q] = src[q];
    }
    sB3[tid] = b3v[(tid & 1)*128 + (tid >> 1)];
    if (tid < 64){ sG[tid] = g2[tid]; sBe[tid] = bb2[tid]; }
    else if (tid < 128) sB4[tid-64] = b4v[tid-64];
    else if (tid < 192) sGa[tid-128] = gamma[tid-128];
    __syncthreads();

    size_t P0 = (size_t)blockIdx.x * 128;
    {   // LN2 of g_x2 -> A tile
        int px = tid >> 1, half = tid & 1;
        const float4* xp = (const float4*)(g_x2 + (P0 + px) * 64 + half * 32);
        float4 v[8];
        #pragma unroll
        for (int q = 0; q < 8; q++) v[q] = xp[q];
        float s = 0.f, ss = 0.f;
        #pragma unroll
        for (int q = 0; q < 8; q++){
            float4 t = v[q];
            s += t.x + t.y + t.z + t.w;
            ss = fmaf(t.x,t.x, fmaf(t.y,t.y, fmaf(t.z,t.z, fmaf(t.w,t.w, ss))));
        }
        s  += __shfl_xor_sync(0xffffffffu, s, 1);
        ss += __shfl_xor_sync(0xffffffffu, ss, 1);
        float mean = s * (1.f/64.f);
        float var  = fmaf(-mean, mean, ss * (1.f/64.f));
        float rstd = rsqrtf(var + EPSV);
        char* dstrow = smem + px*144 + half*64;
        #pragma unroll
        for (int g = 0; g < 4; g++){
            float4 va = v[2*g], vb = v[2*g+1];
            int c = half*32 + g*8;
            float f0 = fmaf((va.x-mean)*rstd, sG[c+0], sBe[c+0]);
            float f1 = fmaf((va.y-mean)*rstd, sG[c+1], sBe[c+1]);
            float f2 = fmaf((va.z-mean)*rstd, sG[c+2], sBe[c+2]);
            float f3 = fmaf((va.w-mean)*rstd, sG[c+3], sBe[c+3]);
            float f4 = fmaf((vb.x-mean)*rstd, sG[c+4], sBe[c+4]);
            float f5 = fmaf((vb.y-mean)*rstd, sG[c+5], sBe[c+5]);
            float f6 = fmaf((vb.z-mean)*rstd, sG[c+6], sBe[c+6]);
            float f7 = fmaf((vb.w-mean)*rstd, sG[c+7], sBe[c+7]);
            *(uint4*)(dstrow + g*16) = make_uint4(bfpack(f0,f1), bfpack(f2,f3),
                                                  bfpack(f4,f5), bfpack(f6,f7));
        }
    }
    __syncthreads();

    {   // phase 1: pw3 GEMM + gate -> smem
        int ns = wid * 32;
        int br = lane & 7, bg = (lane >> 3) & 1;
        uint32_t bfr[4][4][2];
        #pragma unroll
        for (int nt = 0; nt < 4; nt++)
            #pragma unroll
            for (int kt = 0; kt < 4; kt++)
                ldsm2(bfr[nt][kt], sb + K4B_SW3_OFF + (ns + nt*8 + br)*144 + bg*16 + kt*32);

        int ag = lane >> 3, ar = lane & 7;
        uint32_t abase = sb + (ar + (ag & 1)*8)*144 + (ag >> 1)*16;
        #pragma unroll 1
        for (int mt = 0; mt < 8; mt++){
            uint32_t af[4][4];
            #pragma unroll
            for (int kt = 0; kt < 4; kt++) ldsm4(af[kt], abase + mt*2304 + kt*32);
            float acc[4][4];
            #pragma unroll
            for (int nt = 0; nt < 4; nt++){ acc[nt][0]=0.f; acc[nt][1]=0.f; acc[nt][2]=0.f; acc[nt][3]=0.f; }
            #pragma unroll
            for (int kt = 0; kt < 4; kt++)
                #pragma unroll
                for (int nt = 0; nt < 4; nt++)
                    mma16816(acc[nt], af[kt], bfr[nt][kt]);
            int r0 = mt*16 + (lane >> 2);
            int c0 = ns + (lane & 3)*2;
            char* g0 = smem + K4B_GT_OFF + r0*272;
            char* g1 = g0 + 8*272;
            #pragma unroll
            for (int nt = 0; nt < 4; nt++){
                int c = c0 + nt*8;
                float ga = (acc[nt][0] + sB3[c]) * (acc[nt][1] + sB3[c+1]);
                float gb = (acc[nt][2] + sB3[c]) * (acc[nt][3] + sB3[c+1]);
                *(__nv_bfloat16*)(g0 + (c >> 1)*2) = __float2bfloat16(ga);
                *(__nv_bfloat16*)(g1 + (c >> 1)*2) = __float2bfloat16(gb);
            }
        }
    }
    __syncthreads();

    {   // phase 2: pw4 GEMM + gamma residual -> out
        int n0 = wid * 8;
        int br = lane & 7, bg = (lane >> 3) & 1;
        uint32_t bfr[8][2];
        #pragma unroll
        for (int kt = 0; kt < 8; kt++)
            ldsm2(bfr[kt], sb + K4B_SW4_OFF + (n0 + br)*272 + bg*16 + kt*32);

        int ag = lane >> 3, ar = lane & 7;
        uint32_t abase = sb + K4B_GT_OFF + (ar + (ag & 1)*8)*272 + (ag >> 1)*16;
        #pragma unroll 1
        for (int mt = 0; mt < 8; mt++){
            uint32_t af[8][4];
            #pragma unroll
            for (int kt = 0; kt < 8; kt++) ldsm4(af[kt], abase + mt*4352 + kt*32);
            float acc[4] = {0.f, 0.f, 0.f, 0.f};
            #pragma unroll
            for (int kt = 0; kt < 8; kt++) mma16816(acc, af[kt], bfr[kt]);
            int r0 = mt*16 + (lane >> 2);
            int c0 = n0 + (lane & 3)*2;
            float2 xv0 = *(const float2*)(g_x2 + (P0 + r0)*64 + c0);
            float2 xv1 = *(const float2*)(g_x2 + (P0 + r0 + 8)*64 + c0);
            float2 o0, o1;
            o0.x = fmaf(acc[0] + sB4[c0],   sGa[c0],   xv0.x);
            o0.y = fmaf(acc[1] + sB4[c0+1], sGa[c0+1], xv0.y);
            o1.x = fmaf(acc[2] + sB4[c0],   sGa[c0],   xv1.x);
            o1.y = fmaf(acc[3] + sB4[c0+1], sGa[c0+1], xv1.y);
            *(float2*)(out + (P0 + r0)*64 + c0)     = o0;
            *(float2*)(out + (P0 + r0 + 8)*64 + c0) = o1;
        }
    }
}

// ---------------------------------------------------------------------------
extern "C" void kernel_launch(void* const* d_in, const int* in_sizes, int n_in,
                              void* d_out, int out_size)
{
    const float* x    = (const float*)d_in[0];
    const float* ln1g = (const float*)d_in[1];
    const float* ln1b = (const float*)d_in[2];
    const float* pw1w = (const float*)d_in[3];
    const float* pw1b = (const float*)d_in[4];
    const float* dww  = (const float*)d_in[5];
    const float* dwb  = (const float*)d_in[6];
    const float* scaw = (const float*)d_in[7];
    const float* scab = (const float*)d_in[8];
    const float* pw2w = (const float*)d_in[9];
    const float* pw2b = (const float*)d_in[10];
    const float* beta = (const float*)d_in[11];
    const float* ln2g = (const float*)d_in[12];
    const float* ln2b = (const float*)d_in[13];
    const float* pw3w = (const float*)d_in[14];
    const float* pw3b = (const float*)d_in[15];
    const float* pw4w = (const float*)d_in[16];
    const float* pw4b = (const float*)d_in[17];
    const float* gam  = (const float*)d_in[18];
    float* out = (float*)d_out;

    cudaFuncSetAttribute(k1_ln_pw1,   cudaFuncAttributeMaxDynamicSharedMemorySize, K1_SMEM);
    cudaFuncSetAttribute(k4a_att_pw2, cudaFuncAttributeMaxDynamicSharedMemorySize, K4A_SMEM);
    cudaFuncSetAttribute(k4b_fused,   cudaFuncAttributeMaxDynamicSharedMemorySize, K4B_SMEM);

    k0_prep    <<<192, 256>>>(pw1w, pw2w, pw3w, pw4w);
    k1_ln_pw1  <<<NPIX/128, 256, K1_SMEM>>>(x, ln1g, ln1b, pw1b);
    k2_dw_gate <<<2048, 128>>>(dww, dwb);
    k3a_reduce <<<128, 128>>>();
    k3b_sca    <<<BB, 128>>>(scaw, scab);
    k4a_att_pw2<<<NPIX/128, 256, K4A_SMEM>>>(x, pw2b, beta);
    k4b_fused  <<<NPIX/128, 256, K4B_SMEM>>>(pw3b, ln2g, ln2b, pw4b, gam, out);
}